// round 11
// baseline (speedup 1.0000x reference)
#include <cuda_runtime.h>
#include <cuda_fp16.h>
#include <math.h>

// Problem dims (fixed by reference setup_inputs)
#define BB 64
#define FF 128
#define TT 4096
#define KK 13
#define NN (BB*TT)   // 262144 samples per coefficient
#define T2 (TT/2)

// ---- device scratch (static: no allocation allowed; zero-init at load) ----
__device__ __half   g_cT16[(size_t)KK * NN];   // cepstra fp16, layout [k][b*T+t]
__device__ __half   g_cP16[(size_t)KK * NN];
__device__ double   g_sum[2][KK];
__device__ double   g_sumsq[2][KK];
__device__ double   g_mcd_acc;
__device__ unsigned g_count;

// ---------------------------------------------------------------------------
// Compile-time DCT basis: weights become FFMA immediates (rt_SMSP=1, no LDS).
// w[k][f] multiplies (x[f] +/- x[127-f]); dct scale and ln2 folded in.
// ---------------------------------------------------------------------------
constexpr double CPI = 3.14159265358979323846264338327950288;

constexpr double ckcos(double x) {
    // range-reduce to [-pi, pi], then Taylor (double-accurate for |x|<=pi)
    while (x >  CPI) x -= 2.0 * CPI;
    while (x < -CPI) x += 2.0 * CPI;
    double t = 1.0, s = 1.0, x2 = x * x;
    for (int i = 1; i <= 24; i++) {
        t *= -x2 / (double)((2*i - 1) * (2*i));
        s += t;
    }
    return s;
}

struct WTab { float w[KK][FF/2]; };

constexpr WTab make_wtab() {
    WTab t{};
    for (int k = 0; k < KK; k++) {
        // sqrt(1/128), sqrt(2/128) = 0.125 exactly; ln2 folded (we use log2)
        double scale = (k == 0) ? 0.088388347648318446545 : 0.125;
        for (int f = 0; f < FF/2; f++) {
            double ang = CPI * (double)((2*f + 1) * k) / 256.0;
            t.w[k][f] = (float)(ckcos(ang) * scale * 0.69314718055994530942);
        }
    }
    return t;
}

__device__ constexpr WTab WT = make_wtab();

// ---------------------------------------------------------------------------
// K1: log2(1+|x|) -> folded 13-pt DCT with immediate-weight FFMAs,
// fp16 cepstra out, fused per-coefficient stats.
// blockIdx.z selects tensor (0=true, 1=pred) -> 26 accums/thread.
// Fully unrolled f loop in chunks of 4 with software prefetch.
// Grid: (TT/512, BB, 2) x 256; each thread owns 2 adjacent t (float2).
// ---------------------------------------------------------------------------
__global__ __launch_bounds__(256) void k1_dct(const float* __restrict__ xt,
                                              const float* __restrict__ xp) {
    const int   b   = blockIdx.y;
    const int   z   = blockIdx.z;
    const float* src = z ? xp : xt;
    __half*      dst = z ? g_cP16 : g_cT16;

    const int t2 = blockIdx.x * blockDim.x + threadIdx.x;   // float2 idx along T
    const float2* px = (const float2*)(src + (size_t)b * FF * TT) + t2;

    float ax[KK], ay[KK];
#pragma unroll
    for (int k = 0; k < KK; k++) { ax[k] = 0.f; ay[k] = 0.f; }

    const int PF = 4;
    float2 bl[PF], bh[PF];
#pragma unroll
    for (int j = 0; j < PF; j++) {
        bl[j] = __ldcs(px + (size_t)j * T2);
        bh[j] = __ldcs(px + (size_t)(FF-1-j) * T2);
    }

#pragma unroll
    for (int f0 = 0; f0 < FF/2; f0 += PF) {
        float2 cl[PF], ch[PF];
#pragma unroll
        for (int j = 0; j < PF; j++) { cl[j] = bl[j]; ch[j] = bh[j]; }
        if (f0 + PF < FF/2) {
#pragma unroll
            for (int j = 0; j < PF; j++) {
                bl[j] = __ldcs(px + (size_t)(f0 + PF + j) * T2);
                bh[j] = __ldcs(px + (size_t)(FF-1 - (f0 + PF + j)) * T2);
            }
        }
#pragma unroll
        for (int j = 0; j < PF; j++) {
            float llx = __log2f(1.0f + fabsf(cl[j].x));
            float lly = __log2f(1.0f + fabsf(cl[j].y));
            float lhx = __log2f(1.0f + fabsf(ch[j].x));
            float lhy = __log2f(1.0f + fabsf(ch[j].y));
            float sx = llx + lhx, dx = llx - lhx;
            float sy = lly + lhy, dy = lly - lhy;
#pragma unroll
            for (int k = 0; k < KK; k++) {
                const float w = WT.w[k][f0 + j];   // compile-time immediate
                if (k & 1) {
                    ax[k] = fmaf(w, dx, ax[k]);
                    ay[k] = fmaf(w, dy, ay[k]);
                } else {
                    ax[k] = fmaf(w, sx, ax[k]);
                    ay[k] = fmaf(w, sy, ay[k]);
                }
            }
        }
    }

    // write fp16 cepstra (coalesced half2 per k)
    const int n2 = b * T2 + t2;
#pragma unroll
    for (int k = 0; k < KK; k++)
        ((__half2*)(dst + (size_t)k * NN))[n2] = __floats2half2_rn(ax[k], ay[k]);

    // ---- fused stats: warp reduce -> shared -> one double atomic per k
    __shared__ float shS[KK], shQ[KK];
    if (threadIdx.x < KK) { shS[threadIdx.x] = 0.f; shQ[threadIdx.x] = 0.f; }
    __syncthreads();

    const int lane = threadIdx.x & 31;
#pragma unroll
    for (int k = 0; k < KK; k++) {
        float s = ax[k] + ay[k];
        float q = fmaf(ax[k], ax[k], ay[k] * ay[k]);
#pragma unroll
        for (int o = 16; o > 0; o >>= 1) {
            s += __shfl_down_sync(0xffffffffu, s, o);
            q += __shfl_down_sync(0xffffffffu, q, o);
        }
        if (lane == 0) { atomicAdd(&shS[k], s); atomicAdd(&shQ[k], q); }
    }
    __syncthreads();
    if (threadIdx.x < KK) {
        atomicAdd(&g_sum[z][threadIdx.x],   (double)shS[threadIdx.x]);
        atomicAdd(&g_sumsq[z][threadIdx.x], (double)shQ[threadIdx.x]);
    }
}

// ---------------------------------------------------------------------------
// K2: finalize stats (redundant per-block, double), mcd over all (b,t);
// last block writes the scalar and resets accumulators for the next replay.
// Grid 1024 x 256 — ONE sample per thread (max occupancy; K2 is latency-bound).
// ---------------------------------------------------------------------------
__global__ __launch_bounds__(256) void k2_mcd(float* __restrict__ out) {
    __shared__ float srT[KK], srP[KK], soff[KK];
    if (threadIdx.x < KK) {
        int k = threadIdx.x;
        double sT = g_sum[0][k];
        double mT = sT / (double)NN;
        double vT = (g_sumsq[0][k] - sT * sT / (double)NN) / (double)(NN - 1);
        if (vT < 0.0) vT = 0.0;
        double rT = 1.0 / (sqrt(vT) + 1e-6);
        double sP = g_sum[1][k];
        double mP = sP / (double)NN;
        double vP = (g_sumsq[1][k] - sP * sP / (double)NN) / (double)(NN - 1);
        if (vP < 0.0) vP = 0.0;
        double rP = 1.0 / (sqrt(vP) + 1e-6);
        srT[k]  = (float)rT;
        srP[k]  = (float)rP;
        soff[k] = (float)(mT * rT - mP * rP);
    }
    __syncthreads();

    const int n = blockIdx.x * blockDim.x + threadIdx.x;   // 0 .. NN-1 exact

    float s = 0.f;
#pragma unroll
    for (int k = 0; k < KK; k++) {
        float cT = __half2float(g_cT16[(size_t)k * NN + n]);
        float cP = __half2float(g_cP16[(size_t)k * NN + n]);
        float d  = fmaf(cT, srT[k], -soff[k]) - cP * srP[k];
        s = fmaf(d, d, s);
    }
    float acc = sqrtf(2.0f * s);

    __shared__ float sh_acc;
    if (threadIdx.x == 0) sh_acc = 0.f;
    __syncthreads();
#pragma unroll
    for (int o = 16; o > 0; o >>= 1) acc += __shfl_down_sync(0xffffffffu, acc, o);
    if ((threadIdx.x & 31) == 0) atomicAdd(&sh_acc, acc);
    __syncthreads();

    if (threadIdx.x == 0) {
        atomicAdd(&g_mcd_acc, (double)sh_acc);
        __threadfence();
        unsigned done = atomicAdd(&g_count, 1u);
        if (done == gridDim.x - 1) {
            double total = atomicAdd(&g_mcd_acc, 0.0);
            out[0] = (float)(total * 4.342944819032518 / (double)NN);  // 10/ln10, /N
            // reset state for the next graph replay (first call uses load-time zeros)
            for (int k = 0; k < KK; k++) {
                g_sum[0][k] = 0.0; g_sum[1][k] = 0.0;
                g_sumsq[0][k] = 0.0; g_sumsq[1][k] = 0.0;
            }
            g_mcd_acc = 0.0;
            __threadfence();
            g_count = 0u;
        }
    }
}

extern "C" void kernel_launch(void* const* d_in, const int* in_sizes, int n_in,
                              void* d_out, int out_size) {
    const float* mel_true = (const float*)d_in[0];
    const float* mel_pred = (const float*)d_in[1];
    float* out = (float*)d_out;

    dim3 g1(TT / 512, BB, 2);        // 8 x 64 x 2 = 1024 blocks, 2 t per thread
    k1_dct<<<g1, 256>>>(mel_true, mel_pred);

    k2_mcd<<<1024, 256>>>(out);      // 1 sample per thread, exact cover
}

// round 12
// speedup vs baseline: 1.0758x; 1.0758x over previous
#include <cuda_runtime.h>
#include <cuda_fp16.h>
#include <math.h>

// Problem dims (fixed by reference setup_inputs)
#define BB 64
#define FF 128
#define TT 4096
#define KK 13
#define NN (BB*TT)   // 262144 samples per coefficient
#define T2 (TT/2)

// ---- device scratch (static: no allocation allowed; zero-init at load) ----
// n-major cepstra: one 32B struct per sample = 13 fp16 coeffs + 3 pad.
__device__ __half   g_cT32[(size_t)NN * 16];
__device__ __half   g_cP32[(size_t)NN * 16];
__device__ double   g_sum[2][KK];
__device__ double   g_sumsq[2][KK];
__device__ double   g_mcd_acc;
__device__ unsigned g_count;

// ---- packed fp32x2 helpers (Blackwell FFMA2 via PTX) ----
__device__ __forceinline__ unsigned long long pack2(float x, float y) {
    unsigned long long r;
    asm("mov.b64 %0, {%1, %2};" : "=l"(r) : "f"(x), "f"(y));
    return r;
}
__device__ __forceinline__ void unpack2(unsigned long long v, float& x, float& y) {
    asm("mov.b64 {%0, %1}, %2;" : "=f"(x), "=f"(y) : "l"(v));
}
__device__ __forceinline__ void fma2(unsigned long long& a,
                                     unsigned long long w,
                                     unsigned long long v) {
    asm("fma.rn.f32x2 %0, %1, %2, %0;" : "+l"(a) : "l"(w), "l"(v));
}

// pack 13 floats (+3 zero pad) into two uint4 as fp16
__device__ __forceinline__ void pack13(const float* v, uint4& u0, uint4& u1) {
    __half2* h0 = (__half2*)&u0;
    __half2* h1 = (__half2*)&u1;
    h0[0] = __floats2half2_rn(v[0],  v[1]);
    h0[1] = __floats2half2_rn(v[2],  v[3]);
    h0[2] = __floats2half2_rn(v[4],  v[5]);
    h0[3] = __floats2half2_rn(v[6],  v[7]);
    h1[0] = __floats2half2_rn(v[8],  v[9]);
    h1[1] = __floats2half2_rn(v[10], v[11]);
    h1[2] = __floats2half2_rn(v[12], 0.f);
    h1[3] = __floats2half2_rn(0.f,   0.f);
}

// ---------------------------------------------------------------------------
// K1: log2(1+|x|) -> folded 13-pt DCT (packed f32x2 FMAs), n-major fp16
// cepstra out (4x STG.128 per thread), fused per-coefficient stats.
// blockIdx.z selects tensor (0=true, 1=pred). Basis in smem as {w,w} pairs.
// 4-deep software prefetch of the (f, 127-f) row pairs.
// Grid: (TT/512, BB, 2) x 256; each thread owns 2 adjacent t (float2).
// ---------------------------------------------------------------------------
__global__ __launch_bounds__(256) void k1_dct(const float* __restrict__ xt,
                                              const float* __restrict__ xp) {
    __shared__ float2 sb[KK][FF/2];     // {w, w} duplicated
    for (int i = threadIdx.x; i < KK * (FF/2); i += blockDim.x) {
        int k = i >> 6, f = i & 63;
        // sqrt(1/128), sqrt(2/128)=0.125 ; ln2 folded in (we use log2)
        float scale = (k == 0) ? 0.088388347648318447f : 0.125f;
        float w = cospif((float)((2*f + 1) * k) * (1.0f/256.0f))
                * scale * 0.69314718055994531f;
        sb[k][f] = make_float2(w, w);
    }
    __syncthreads();

    const int   b   = blockIdx.y;
    const int   z   = blockIdx.z;
    const float* src = z ? xp : xt;
    __half*      dst = z ? g_cP32 : g_cT32;

    const int t2 = blockIdx.x * blockDim.x + threadIdx.x;   // float2 idx along T
    const float2* px = (const float2*)(src + (size_t)b * FF * TT) + t2;

    unsigned long long acc[KK];   // packed (ax, ay) fp32 pairs
#pragma unroll
    for (int k = 0; k < KK; k++) acc[k] = 0ull;

    const int PF = 4;
    float2 bl[PF], bh[PF];
#pragma unroll
    for (int j = 0; j < PF; j++) {
        bl[j] = __ldcs(px + (size_t)j * T2);
        bh[j] = __ldcs(px + (size_t)(FF-1-j) * T2);
    }

#pragma unroll 1
    for (int f0 = 0; f0 < FF/2; f0 += PF) {
        float2 cl[PF], ch[PF];
#pragma unroll
        for (int j = 0; j < PF; j++) { cl[j] = bl[j]; ch[j] = bh[j]; }
        if (f0 + PF < FF/2) {
#pragma unroll
            for (int j = 0; j < PF; j++) {
                bl[j] = __ldcs(px + (size_t)(f0 + PF + j) * T2);
                bh[j] = __ldcs(px + (size_t)(FF-1 - (f0 + PF + j)) * T2);
            }
        }
#pragma unroll
        for (int j = 0; j < PF; j++) {
            float llx = __log2f(1.0f + fabsf(cl[j].x));
            float lly = __log2f(1.0f + fabsf(cl[j].y));
            float lhx = __log2f(1.0f + fabsf(ch[j].x));
            float lhy = __log2f(1.0f + fabsf(ch[j].y));
            unsigned long long vs = pack2(llx + lhx, lly + lhy);
            unsigned long long vd = pack2(llx - lhx, lly - lhy);
            const unsigned long long* wrow =
                (const unsigned long long*)&sb[0][f0 + j];
#pragma unroll
            for (int k = 0; k < KK; k++) {
                // sb is [KK][64] float2 -> row stride 64 in ull units
                unsigned long long w = wrow[(size_t)k * (FF/2)];
                fma2(acc[k], w, (k & 1) ? vd : vs);
            }
        }
    }

    // unpack accumulators
    float ax[KK], ay[KK];
#pragma unroll
    for (int k = 0; k < KK; k++) unpack2(acc[k], ax[k], ay[k]);

    // n-major store: samples n=2*n2 (ax) and n=2*n2+1 (ay), 64B contiguous
    const int n2 = b * T2 + t2;
    uint4 u0, u1, u2, u3;
    pack13(ax, u0, u1);
    pack13(ay, u2, u3);
    uint4* op = (uint4*)(dst) + (size_t)n2 * 4;
    op[0] = u0; op[1] = u1; op[2] = u2; op[3] = u3;

    // ---- fused stats: warp reduce -> shared -> one double atomic per k
    __shared__ float shS[KK], shQ[KK];
    if (threadIdx.x < KK) { shS[threadIdx.x] = 0.f; shQ[threadIdx.x] = 0.f; }
    __syncthreads();

    const int lane = threadIdx.x & 31;
#pragma unroll
    for (int k = 0; k < KK; k++) {
        float s = ax[k] + ay[k];
        float q = fmaf(ax[k], ax[k], ay[k] * ay[k]);
#pragma unroll
        for (int o = 16; o > 0; o >>= 1) {
            s += __shfl_down_sync(0xffffffffu, s, o);
            q += __shfl_down_sync(0xffffffffu, q, o);
        }
        if (lane == 0) { atomicAdd(&shS[k], s); atomicAdd(&shQ[k], q); }
    }
    __syncthreads();
    if (threadIdx.x < KK) {
        atomicAdd(&g_sum[z][threadIdx.x],   (double)shS[threadIdx.x]);
        atomicAdd(&g_sumsq[z][threadIdx.x], (double)shQ[threadIdx.x]);
    }
}

// ---------------------------------------------------------------------------
// K2: finalize stats (redundant per-block, double), mcd over all (b,t);
// last block writes the scalar and resets accumulators for the next replay.
// Grid 1024 x 256 — one sample per thread, 4x LDG.128 (n-major structs).
// ---------------------------------------------------------------------------
__global__ __launch_bounds__(256) void k2_mcd(float* __restrict__ out) {
    __shared__ float srT[KK], srP[KK], soff[KK];
    if (threadIdx.x < KK) {
        int k = threadIdx.x;
        double sT = g_sum[0][k];
        double mT = sT / (double)NN;
        double vT = (g_sumsq[0][k] - sT * sT / (double)NN) / (double)(NN - 1);
        if (vT < 0.0) vT = 0.0;
        double rT = 1.0 / (sqrt(vT) + 1e-6);
        double sP = g_sum[1][k];
        double mP = sP / (double)NN;
        double vP = (g_sumsq[1][k] - sP * sP / (double)NN) / (double)(NN - 1);
        if (vP < 0.0) vP = 0.0;
        double rP = 1.0 / (sqrt(vP) + 1e-6);
        srT[k]  = (float)rT;
        srP[k]  = (float)rP;
        soff[k] = (float)(mT * rT - mP * rP);
    }
    __syncthreads();

    const int n = blockIdx.x * blockDim.x + threadIdx.x;   // 0 .. NN-1 exact

    const uint4* pT = (const uint4*)g_cT32 + (size_t)n * 2;
    const uint4* pP = (const uint4*)g_cP32 + (size_t)n * 2;
    uint4 a0 = pT[0], a1 = pT[1];
    uint4 b0 = pP[0], b1 = pP[1];

    float cT[14], cP[14];
    {
        const __half2* hT0 = (const __half2*)&a0;
        const __half2* hT1 = (const __half2*)&a1;
        const __half2* hP0 = (const __half2*)&b0;
        const __half2* hP1 = (const __half2*)&b1;
#pragma unroll
        for (int j = 0; j < 4; j++) {
            float2 t0 = __half22float2(hT0[j]);
            float2 p0 = __half22float2(hP0[j]);
            cT[2*j] = t0.x;   cT[2*j+1] = t0.y;
            cP[2*j] = p0.x;   cP[2*j+1] = p0.y;
        }
#pragma unroll
        for (int j = 0; j < 3; j++) {
            float2 t1 = __half22float2(hT1[j]);
            float2 p1 = __half22float2(hP1[j]);
            cT[8+2*j] = t1.x; cT[8+2*j+1] = t1.y;
            cP[8+2*j] = p1.x; cP[8+2*j+1] = p1.y;
        }
    }

    float s = 0.f;
#pragma unroll
    for (int k = 0; k < KK; k++) {
        float d = fmaf(cT[k], srT[k], -soff[k]) - cP[k] * srP[k];
        s = fmaf(d, d, s);
    }
    float acc = sqrtf(2.0f * s);

    __shared__ float sh_acc;
    if (threadIdx.x == 0) sh_acc = 0.f;
    __syncthreads();
#pragma unroll
    for (int o = 16; o > 0; o >>= 1) acc += __shfl_down_sync(0xffffffffu, acc, o);
    if ((threadIdx.x & 31) == 0) atomicAdd(&sh_acc, acc);
    __syncthreads();

    if (threadIdx.x == 0) {
        atomicAdd(&g_mcd_acc, (double)sh_acc);
        __threadfence();
        unsigned done = atomicAdd(&g_count, 1u);
        if (done == gridDim.x - 1) {
            double total = atomicAdd(&g_mcd_acc, 0.0);
            out[0] = (float)(total * 4.342944819032518 / (double)NN);  // 10/ln10, /N
            // reset state for the next graph replay (first call uses load-time zeros)
            for (int k = 0; k < KK; k++) {
                g_sum[0][k] = 0.0; g_sum[1][k] = 0.0;
                g_sumsq[0][k] = 0.0; g_sumsq[1][k] = 0.0;
            }
            g_mcd_acc = 0.0;
            __threadfence();
            g_count = 0u;
        }
    }
}

extern "C" void kernel_launch(void* const* d_in, const int* in_sizes, int n_in,
                              void* d_out, int out_size) {
    const float* mel_true = (const float*)d_in[0];
    const float* mel_pred = (const float*)d_in[1];
    float* out = (float*)d_out;

    dim3 g1(TT / 512, BB, 2);        // 8 x 64 x 2 = 1024 blocks, 2 t per thread
    k1_dct<<<g1, 256>>>(mel_true, mel_pred);

    k2_mcd<<<1024, 256>>>(out);      // 1 sample per thread, exact cover
}